// round 1
// baseline (speedup 1.0000x reference)
#include <cuda_runtime.h>
#include <math.h>
#include <stdint.h>

#define NMAX 200000
#define NB 4
#define TOPK 1024
#define BINS 16384
#define CAP 4096
#define THR 0.1f

// ---------------- device scratch (no allocations allowed) ----------------
__device__ float g_score[NMAX];
__device__ float g_box[NMAX][7];
__device__ int   g_hist[NB][BINS];
__device__ int   g_thr[NB];
__device__ int   g_cnt[NB];
__device__ unsigned long long g_cand[NB][CAP];
__device__ float g_nms[NB][TOPK][5];       // x1,x2,y1,y2,area
__device__ float g_top[NB][TOPK][8];       // box7 + score (unmasked)
__device__ unsigned g_mask[NB][32][TOPK];  // [batch][word][row]  (word-major)

// ---------------- kernel Z: zero counters/histograms ----------------
__global__ void k_zero() {
    int i = blockIdx.x * blockDim.x + threadIdx.x;
    int tot = NB * BINS;
    int stride = gridDim.x * blockDim.x;
    int* h = (int*)g_hist;
    for (int j = i; j < tot; j += stride) h[j] = 0;
    if (i < NB) g_cnt[i] = 0;
}

// ---------------- kernel A: per-point GEMV + decode + histogram ----------------
__global__ __launch_bounds__(128) void k_point(
    const float* __restrict__ feat, const int* __restrict__ bidx,
    const int* __restrict__ coor, const float* __restrict__ Wc,
    const float* __restrict__ bc, const float* __restrict__ Wr,
    const float* __restrict__ br, int N)
{
    int lane = threadIdx.x & 31;
    int warp = blockIdx.x * (blockDim.x >> 5) + (threadIdx.x >> 5);
    int nwarps = gridDim.x * (blockDim.x >> 5);

    // register-cache weights for this lane's fixed 8 features
    float w[8][11];
#pragma unroll
    for (int k = 0; k < 8; k++) {
        int c = lane * 8 + k;
        w[k][0] = Wc[c * 2 + 0];
        w[k][1] = Wc[c * 2 + 1];
#pragma unroll
        for (int o = 0; o < 9; o++) w[k][2 + o] = Wr[c * 9 + o];
    }
    float bc0 = bc[0], bc1 = bc[1];
    float brg[9];
#pragma unroll
    for (int o = 0; o < 9; o++) brg[o] = br[o];

    for (int p = warp; p < N; p += nwarps) {
        const float4* fp = (const float4*)(feat + (size_t)p * 256 + lane * 8);
        float4 f0 = fp[0], f1 = fp[1];
        float fv[8] = {f0.x, f0.y, f0.z, f0.w, f1.x, f1.y, f1.z, f1.w};
        float acc[11];
#pragma unroll
        for (int o = 0; o < 11; o++) acc[o] = 0.f;
#pragma unroll
        for (int k = 0; k < 8; k++)
#pragma unroll
            for (int o = 0; o < 11; o++) acc[o] = fmaf(fv[k], w[k][o], acc[o]);
#pragma unroll
        for (int off = 16; off > 0; off >>= 1)
#pragma unroll
            for (int o = 0; o < 11; o++)
                acc[o] += __shfl_xor_sync(0xffffffffu, acc[o], off);

        if (lane == 0) {
            float l0 = acc[0] + bc0, l1 = acc[1] + bc1;
            float conf = 1.f / (1.f + expf(l0 - l1));   // softmax p1
            float r0 = acc[2] + brg[0], r1 = acc[3] + brg[1], r2 = acc[4] + brg[2];
            float d0 = acc[5] + brg[3], d1 = acc[6] + brg[4], d2 = acc[7] + brg[5];
            float a0 = acc[8] + brg[6], a1 = acc[9] + brg[7], s8 = acc[10] + brg[8];
            float scr = 1.f / (1.f + expf(-s8));
            float score = conf * scr;
            int b = bidx[p];
            int cx = coor[p * 2 + 0], cy = coor[p * 2 + 1];
            g_box[p][0] = (float)cx * 0.8f + r0;
            g_box[p][1] = (float)cy * 0.8f + r1;
            g_box[p][2] = r2;
            g_box[p][3] = expf(fminf(fmaxf(d0, -6.f), 6.f));
            g_box[p][4] = expf(fminf(fmaxf(d1, -6.f), 6.f));
            g_box[p][5] = expf(fminf(fmaxf(d2, -6.f), 6.f));
            g_box[p][6] = atan2f(a0, a1);
            g_score[p] = score;
            int bin = (int)(score * (float)BINS);
            bin = max(0, min(BINS - 1, bin));
            atomicAdd(&g_hist[b][bin], 1);
        }
    }
}

// ---------------- kernel B: per-batch histogram threshold ----------------
__global__ __launch_bounds__(1024) void k_thresh() {
    int b = blockIdx.x;
    int t = threadIdx.x;
    __shared__ int part[1024];
    __shared__ int sc;
    int s = 0;
#pragma unroll
    for (int i = 0; i < 16; i++) s += g_hist[b][t * 16 + i];
    part[t] = s;
    __syncthreads();
    // suffix-sum (Hillis-Steele)
    for (int d = 1; d < 1024; d <<= 1) {
        int v = part[t] + ((t + d < 1024) ? part[t + d] : 0);
        __syncthreads();
        part[t] = v;
        __syncthreads();
    }
    if (part[t] >= TOPK && (t == 1023 || part[t + 1] < TOPK)) sc = t;
    if (t == 0 && part[0] < TOPK) sc = -1;
    __syncthreads();
    if (t == 0) {
        int c = sc;
        int T = 0;
        if (c >= 0) {
            int acc = (c == 1023) ? 0 : part[c + 1];
            T = c * 16;
            for (int bin = c * 16 + 15; bin >= c * 16; bin--) {
                acc += g_hist[b][bin];
                if (acc >= TOPK) { T = bin; break; }
            }
        }
        g_thr[b] = T;
    }
}

// ---------------- kernel C: compact candidates ----------------
__global__ void k_compact(const int* __restrict__ bidx, int N) {
    int p = blockIdx.x * blockDim.x + threadIdx.x;
    if (p >= N) return;
    float s = g_score[p];
    int b = bidx[p];
    int bin = (int)(s * (float)BINS);
    bin = max(0, min(BINS - 1, bin));
    if (bin >= g_thr[b]) {
        int pos = atomicAdd(&g_cnt[b], 1);
        if (pos < CAP) {
            unsigned si = __float_as_uint(s);
            g_cand[b][pos] =
                ((unsigned long long)si << 32) | (unsigned)(~(unsigned)p);
        }
    }
}

// ---------------- kernel D: per-batch bitonic sort + top-K prep ----------------
__global__ __launch_bounds__(1024) void k_sort(int N) {
    int b = blockIdx.x;
    int t = threadIdx.x;
    __shared__ unsigned long long sk[CAP];
    int cnt = min(g_cnt[b], CAP);
    for (int i = t; i < CAP; i += 1024) sk[i] = (i < cnt) ? g_cand[b][i] : 0ull;
    __syncthreads();
    for (unsigned kk = 2; kk <= CAP; kk <<= 1)
        for (unsigned j = kk >> 1; j > 0; j >>= 1) {
            for (unsigned i = t; i < CAP; i += 1024) {
                unsigned ixj = i ^ j;
                if (ixj > i) {
                    unsigned long long a = sk[i], c = sk[ixj];
                    bool desc = ((i & kk) == 0);
                    if (desc ? (a < c) : (a > c)) { sk[i] = c; sk[ixj] = a; }
                }
            }
            __syncthreads();
        }
    if (t < TOPK) {
        unsigned long long key = sk[t];
        unsigned p = ~(unsigned)(key & 0xffffffffu);
        float score = __uint_as_float((unsigned)(key >> 32));
        float bx[7];
        if (key != 0ull && p < (unsigned)N) {
#pragma unroll
            for (int c = 0; c < 7; c++) bx[c] = g_box[p][c];
        } else {
#pragma unroll
            for (int c = 0; c < 7; c++) bx[c] = 0.f;
            score = 0.f;
        }
#pragma unroll
        for (int c = 0; c < 7; c++) g_top[b][t][c] = bx[c];
        g_top[b][t][7] = score;
        float x = bx[0], y = bx[1], l = bx[3], w = bx[4];
        g_nms[b][t][0] = x - l * 0.5f;
        g_nms[b][t][1] = x + l * 0.5f;
        g_nms[b][t][2] = y - w * 0.5f;
        g_nms[b][t][3] = y + w * 0.5f;
        g_nms[b][t][4] = l * w;
    }
}

// ---------------- kernel E: IoU suppression bitmask ----------------
__global__ __launch_bounds__(256) void k_iou() {
    int b = blockIdx.x;
    int rg = blockIdx.y;  // 32 rows per block
    __shared__ float sx1[TOPK], sx2[TOPK], sy1[TOPK], sy2[TOPK], sa[TOPK];
    int t = threadIdx.x;
    for (int i = t; i < TOPK; i += 256) {
        sx1[i] = g_nms[b][i][0]; sx2[i] = g_nms[b][i][1];
        sy1[i] = g_nms[b][i][2]; sy2[i] = g_nms[b][i][3];
        sa[i]  = g_nms[b][i][4];
    }
    __syncthreads();
    int lane = t & 31, wp = t >> 5;
    for (int rr = 0; rr < 32; rr++) {
        int r = rg * 32 + rr;
        float rx1 = sx1[r], rx2 = sx2[r], ry1 = sy1[r], ry2 = sy2[r], ra = sa[r];
#pragma unroll
        for (int it = 0; it < 4; it++) {
            int col = it * 256 + wp * 32 + lane;
            float ix = fmaxf(fminf(rx2, sx2[col]) - fmaxf(rx1, sx1[col]), 0.f);
            float iy = fmaxf(fminf(ry2, sy2[col]) - fmaxf(ry1, sy1[col]), 0.f);
            float inter = ix * iy;
            float uni = fmaxf(ra + sa[col] - inter, 1e-6f);
            bool sup = inter > THR * uni;  // iou > THR
            unsigned bal = __ballot_sync(0xffffffffu, sup);
            if (lane == 0) g_mask[b][it * 8 + wp][r] = bal;
        }
    }
}

// ---------------- kernel F: sequential NMS reduce + output ----------------
__global__ __launch_bounds__(1024) void k_nms_out(float* __restrict__ out) {
    int b = blockIdx.x;
    int t = threadIdx.x;
    __shared__ unsigned sdiag[TOPK];      // masked bits strictly above r within own word
    __shared__ unsigned char sflag[TOPK]; // row has any suppression bit at col > r
    __shared__ int sslot[TOPK];
    __shared__ unsigned srows[256][32];
    __shared__ unsigned sremv[32];
    __shared__ unsigned skeepw[32];
    __shared__ int scount;
    if (t == 0) scount = 0;
    if (t < 32) sremv[t] = 0;
    __syncthreads();

    {   // preload: flags + staged flagged rows
        int r = t;
        unsigned v[32];
#pragma unroll
        for (int w = 0; w < 32; w++) v[w] = g_mask[b][w][r];
        int wd = r >> 5;
        unsigned above = ~((2u << (r & 31)) - 1u);  // r&31==31 -> 0
        unsigned dg = v[wd] & above;
        sdiag[r] = dg;
        unsigned hi = 0;
#pragma unroll
        for (int w = 0; w < 32; w++)
            if (w > wd) hi |= v[w];
        bool flag = (dg != 0u) || (hi != 0u);
        sflag[r] = (unsigned char)flag;
        int slot = -2;
        if (flag) {
            slot = atomicAdd(&scount, 1);
            if (slot < 256) {
#pragma unroll
                for (int w = 0; w < 32; w++) srows[slot][w] = v[w];
            } else slot = -2;
        }
        sslot[r] = slot;
    }
    __syncthreads();

    if (t < 32) {  // single warp: sequential greedy NMS over 32-row chunks
        int lane = t;
        for (int ch = 0; ch < 32; ch++) {
            unsigned cur = sremv[ch];
            int r = ch * 32 + lane;
            unsigned mym = sdiag[r];
            unsigned intra = __reduce_or_sync(0xffffffffu, mym);
            unsigned keepbits;
            if (intra == 0u) {
                keepbits = ~cur;  // no intra-chunk suppression
            } else {
                unsigned supp = cur;
                keepbits = 0u;
                for (int q = 0; q < 32; q++) {
                    unsigned m = __shfl_sync(0xffffffffu, mym, q);
                    if (!((supp >> q) & 1u)) { keepbits |= (1u << q); supp |= m; }
                }
            }
            if (lane == 0) skeepw[ch] = keepbits;
            bool mykeep = (keepbits >> lane) & 1u;
            unsigned todo = __ballot_sync(0xffffffffu, mykeep && sflag[r]);
            while (todo) {
                int q = __ffs(todo) - 1;
                todo &= todo - 1;
                int rr = ch * 32 + q;
                int slot = sslot[rr];
                unsigned v = (slot >= 0) ? srows[slot][lane] : g_mask[b][lane][rr];
                sremv[lane] |= v;
            }
            __syncwarp();
        }
    }
    __syncthreads();

    {   // write outputs: boxes (4,1024,8), labels (4,1024)=0, keep (4,1024)
        int r = t;
        float kp = ((skeepw[r >> 5] >> (r & 31)) & 1u) ? 1.f : 0.f;
#pragma unroll
        for (int c = 0; c < 8; c++)
            out[((size_t)b * TOPK + r) * 8 + c] = g_top[b][r][c] * kp;
        out[(size_t)NB * TOPK * 8 + (size_t)b * TOPK + r] = 0.f;               // label
        out[(size_t)NB * TOPK * 8 + (size_t)NB * TOPK + (size_t)b * TOPK + r] = kp;  // keep
    }
}

// ---------------- launch ----------------
extern "C" void kernel_launch(void* const* d_in, const int* in_sizes, int n_in,
                              void* d_out, int out_size) {
    const float* feat = (const float*)d_in[0];
    const int*   bidx = (const int*)d_in[1];
    const int*   coor = (const int*)d_in[2];
    const float* Wc   = (const float*)d_in[3];
    const float* bc   = (const float*)d_in[4];
    const float* Wr   = (const float*)d_in[5];
    const float* br   = (const float*)d_in[6];
    float* out = (float*)d_out;
    int N = in_sizes[0] / 256;

    k_zero<<<64, 256>>>();
    k_point<<<1184, 128>>>(feat, bidx, coor, Wc, bc, Wr, br, N);
    k_thresh<<<NB, 1024>>>();
    k_compact<<<(N + 255) / 256, 256>>>(bidx, N);
    k_sort<<<NB, 1024>>>(N);
    dim3 ge(NB, 32);
    k_iou<<<ge, 256>>>();
    k_nms_out<<<NB, 1024>>>(out);
}

// round 3
// speedup vs baseline: 2.4566x; 2.4566x over previous
#include <cuda_runtime.h>
#include <math.h>
#include <stdint.h>

#define NMAX 200000
#define NB 4
#define TOPK 1024
#define BINS 16384
#define CAP 4096
#define THR 0.1f

// ---------------- device scratch ----------------
__device__ float g_score[NMAX];
__device__ int   g_hist[NB][BINS];
__device__ int   g_thr[NB];
__device__ int   g_cnt[NB];
__device__ unsigned long long g_cand[NB][CAP];
__device__ unsigned long long g_sel[NB][TOPK];   // sorted keys (score<<32 | ~p)
__device__ float g_nms[NB][TOPK][5];       // x1,x2,y1,y2,area
__device__ float g_top[NB][TOPK][8];       // box7 + score (unmasked)
__device__ unsigned g_mask[NB][32][TOPK];  // [batch][word][row]

// ---------------- kernel Z: zero counters/histograms ----------------
__global__ void k_zero() {
    int i = blockIdx.x * blockDim.x + threadIdx.x;
    int tot = NB * BINS;
    int stride = gridDim.x * blockDim.x;
    int* h = (int*)g_hist;
    for (int j = i; j < tot; j += stride) h[j] = 0;
    if (i < NB) g_cnt[i] = 0;
}

// ---------------- kernel A1: score-only GEMV (bit-exact round-1 order) ----------------
__global__ __launch_bounds__(256) void k_score(
    const float* __restrict__ feat, const int* __restrict__ bidx,
    const float* __restrict__ Wc, const float* __restrict__ bc,
    const float* __restrict__ Wr, const float* __restrict__ br, int N)
{
    int lane = threadIdx.x & 31;
    int warp = blockIdx.x * (blockDim.x >> 5) + (threadIdx.x >> 5);
    int nwarps = gridDim.x * (blockDim.x >> 5);

    // per-lane weight cache: only the 3 score-relevant outputs
    float wc0[8], wc1[8], ws8[8];
#pragma unroll
    for (int k = 0; k < 8; k++) {
        int c = lane * 8 + k;
        wc0[k] = Wc[c * 2 + 0];
        wc1[k] = Wc[c * 2 + 1];
        ws8[k] = Wr[c * 9 + 8];
    }
    float bc0 = bc[0], bc1 = bc[1];
    float br8 = br[8];

    int p = warp;
    float4 f0, f1;
    if (p < N) {
        const float4* fp = (const float4*)(feat + (size_t)p * 256 + lane * 8);
        f0 = fp[0]; f1 = fp[1];
    }
    while (p < N) {
        int np = p + nwarps;
        float4 n0, n1;
        if (np < N) {
            const float4* fp = (const float4*)(feat + (size_t)np * 256 + lane * 8);
            n0 = fp[0]; n1 = fp[1];
        }
        float fv[8] = {f0.x, f0.y, f0.z, f0.w, f1.x, f1.y, f1.z, f1.w};
        float a0 = 0.f, a1 = 0.f, a10 = 0.f;
#pragma unroll
        for (int k = 0; k < 8; k++) {
            a0 = fmaf(fv[k], wc0[k], a0);
            a1 = fmaf(fv[k], wc1[k], a1);
            a10 = fmaf(fv[k], ws8[k], a10);
        }
#pragma unroll
        for (int off = 16; off > 0; off >>= 1) {
            a0 += __shfl_xor_sync(0xffffffffu, a0, off);
            a1 += __shfl_xor_sync(0xffffffffu, a1, off);
            a10 += __shfl_xor_sync(0xffffffffu, a10, off);
        }
        if (lane == 0) {
            float l0 = a0 + bc0, l1 = a1 + bc1;
            float conf = 1.f / (1.f + expf(l0 - l1));   // softmax p1
            float s8 = a10 + br8;
            float scr = 1.f / (1.f + expf(-s8));
            float score = conf * scr;
            int b = bidx[p];
            g_score[p] = score;
            int bin = (int)(score * (float)BINS);
            bin = max(0, min(BINS - 1, bin));
            atomicAdd(&g_hist[b][bin], 1);
        }
        f0 = n0; f1 = n1; p = np;
    }
}

// ---------------- kernel B: per-batch histogram threshold ----------------
__global__ __launch_bounds__(1024) void k_thresh() {
    int b = blockIdx.x;
    int t = threadIdx.x;
    __shared__ int part[1024];
    __shared__ int sc;
    int s = 0;
#pragma unroll
    for (int i = 0; i < 16; i++) s += g_hist[b][t * 16 + i];
    part[t] = s;
    __syncthreads();
    for (int d = 1; d < 1024; d <<= 1) {
        int v = part[t] + ((t + d < 1024) ? part[t + d] : 0);
        __syncthreads();
        part[t] = v;
        __syncthreads();
    }
    if (part[t] >= TOPK && (t == 1023 || part[t + 1] < TOPK)) sc = t;
    if (t == 0 && part[0] < TOPK) sc = -1;
    __syncthreads();
    if (t == 0) {
        int c = sc;
        int T = 0;
        if (c >= 0) {
            int acc = (c == 1023) ? 0 : part[c + 1];
            T = c * 16;
            for (int bin = c * 16 + 15; bin >= c * 16; bin--) {
                acc += g_hist[b][bin];
                if (acc >= TOPK) { T = bin; break; }
            }
        }
        g_thr[b] = T;
    }
}

// ---------------- kernel C: compact candidates (warp-aggregated) ----------------
__global__ __launch_bounds__(256) void k_compact(const int* __restrict__ bidx, int N) {
    int p = blockIdx.x * blockDim.x + threadIdx.x;
    int lane = threadIdx.x & 31;
    bool pass = false;
    int b = 0;
    unsigned long long key = 0ull;
    if (p < N) {
        float s = g_score[p];
        b = bidx[p];
        int bin = (int)(s * (float)BINS);
        bin = max(0, min(BINS - 1, bin));
        pass = bin >= g_thr[b];
        key = ((unsigned long long)__float_as_uint(s) << 32) | (unsigned)(~(unsigned)p);
    }
#pragma unroll
    for (int bb = 0; bb < NB; bb++) {
        unsigned m = __ballot_sync(0xffffffffu, pass && b == bb);
        if (m) {
            int leader = __ffs(m) - 1;
            int base = 0;
            if (lane == leader) base = atomicAdd(&g_cnt[bb], __popc(m));
            base = __shfl_sync(0xffffffffu, base, leader);
            if (pass && b == bb) {
                int pos = base + __popc(m & ((1u << lane) - 1u));
                if (pos < CAP) g_cand[bb][pos] = key;
            }
        }
    }
}

// ---------------- kernel D: per-batch bitonic sort ----------------
__global__ __launch_bounds__(1024) void k_sort() {
    int b = blockIdx.x;
    int t = threadIdx.x;
    __shared__ unsigned long long sk[CAP];
    int cnt = min(g_cnt[b], CAP);
    int size = TOPK;
    while (size < cnt) size <<= 1;
    for (int i = t; i < size; i += 1024) sk[i] = (i < cnt) ? g_cand[b][i] : 0ull;
    __syncthreads();
    for (unsigned kk = 2; kk <= (unsigned)size; kk <<= 1)
        for (unsigned j = kk >> 1; j > 0; j >>= 1) {
            for (unsigned i = t; i < (unsigned)size; i += 1024) {
                unsigned ixj = i ^ j;
                if (ixj > i) {
                    unsigned long long a = sk[i], c = sk[ixj];
                    bool desc = ((i & kk) == 0);
                    if (desc ? (a < c) : (a > c)) { sk[i] = c; sk[ixj] = a; }
                }
            }
            __syncthreads();
        }
    if (t < TOPK) g_sel[b][t] = sk[t];
}

// ---------------- kernel A2: decode boxes for selected points (bit-exact) ----------------
__global__ __launch_bounds__(256) void k_decode(
    const float* __restrict__ feat, const int* __restrict__ coor,
    const float* __restrict__ Wr, const float* __restrict__ br, int N)
{
    int lane = threadIdx.x & 31;
    int warp = blockIdx.x * (blockDim.x >> 5) + (threadIdx.x >> 5); // 0..4095
    int b = warp >> 10;
    int t = warp & (TOPK - 1);
    if (b >= NB) return;

    unsigned long long key = g_sel[b][t];
    unsigned p = ~(unsigned)(key & 0xffffffffu);
    float score = __uint_as_float((unsigned)(key >> 32));
    bool valid = (key != 0ull) && (p < (unsigned)N);

    float bx[7];
    if (valid) {
        float w[8][9];
#pragma unroll
        for (int k = 0; k < 8; k++) {
            int c = lane * 8 + k;
#pragma unroll
            for (int o = 0; o < 9; o++) w[k][o] = Wr[c * 9 + o];
        }
        const float4* fp = (const float4*)(feat + (size_t)p * 256 + lane * 8);
        float4 f0 = fp[0], f1 = fp[1];
        float fv[8] = {f0.x, f0.y, f0.z, f0.w, f1.x, f1.y, f1.z, f1.w};
        float acc[9];
#pragma unroll
        for (int o = 0; o < 9; o++) acc[o] = 0.f;
#pragma unroll
        for (int k = 0; k < 8; k++)
#pragma unroll
            for (int o = 0; o < 9; o++) acc[o] = fmaf(fv[k], w[k][o], acc[o]);
#pragma unroll
        for (int off = 16; off > 0; off >>= 1)
#pragma unroll
            for (int o = 0; o < 9; o++)
                acc[o] += __shfl_xor_sync(0xffffffffu, acc[o], off);

        float r0 = acc[0] + br[0], r1 = acc[1] + br[1], r2 = acc[2] + br[2];
        float d0 = acc[3] + br[3], d1 = acc[4] + br[4], d2 = acc[5] + br[5];
        float a0 = acc[6] + br[6], a1 = acc[7] + br[7];
        int cx = coor[p * 2 + 0], cy = coor[p * 2 + 1];
        bx[0] = (float)cx * 0.8f + r0;
        bx[1] = (float)cy * 0.8f + r1;
        bx[2] = r2;
        bx[3] = expf(fminf(fmaxf(d0, -6.f), 6.f));
        bx[4] = expf(fminf(fmaxf(d1, -6.f), 6.f));
        bx[5] = expf(fminf(fmaxf(d2, -6.f), 6.f));
        bx[6] = atan2f(a0, a1);
    } else {
#pragma unroll
        for (int c = 0; c < 7; c++) bx[c] = 0.f;
        score = 0.f;
    }
    if (lane == 0) {
#pragma unroll
        for (int c = 0; c < 7; c++) g_top[b][t][c] = bx[c];
        g_top[b][t][7] = score;
        float x = bx[0], y = bx[1], l = bx[3], w = bx[4];
        g_nms[b][t][0] = x - l * 0.5f;
        g_nms[b][t][1] = x + l * 0.5f;
        g_nms[b][t][2] = y - w * 0.5f;
        g_nms[b][t][3] = y + w * 0.5f;
        g_nms[b][t][4] = l * w;
    }
}

// ---------------- kernel E: IoU suppression bitmask ----------------
__global__ __launch_bounds__(256) void k_iou() {
    int b = blockIdx.x;
    int rg = blockIdx.y;
    __shared__ float sx1[TOPK], sx2[TOPK], sy1[TOPK], sy2[TOPK], sa[TOPK];
    int t = threadIdx.x;
    for (int i = t; i < TOPK; i += 256) {
        sx1[i] = g_nms[b][i][0]; sx2[i] = g_nms[b][i][1];
        sy1[i] = g_nms[b][i][2]; sy2[i] = g_nms[b][i][3];
        sa[i]  = g_nms[b][i][4];
    }
    __syncthreads();
    int lane = t & 31, wp = t >> 5;
    for (int rr = 0; rr < 32; rr++) {
        int r = rg * 32 + rr;
        float rx1 = sx1[r], rx2 = sx2[r], ry1 = sy1[r], ry2 = sy2[r], ra = sa[r];
#pragma unroll
        for (int it = 0; it < 4; it++) {
            int col = it * 256 + wp * 32 + lane;
            float ix = fmaxf(fminf(rx2, sx2[col]) - fmaxf(rx1, sx1[col]), 0.f);
            float iy = fmaxf(fminf(ry2, sy2[col]) - fmaxf(ry1, sy1[col]), 0.f);
            float inter = ix * iy;
            float uni = fmaxf(ra + sa[col] - inter, 1e-6f);
            bool sup = inter > THR * uni;
            unsigned bal = __ballot_sync(0xffffffffu, sup);
            if (lane == 0) g_mask[b][it * 8 + wp][r] = bal;
        }
    }
}

// ---------------- kernel F: sequential NMS reduce + output ----------------
__global__ __launch_bounds__(1024) void k_nms_out(float* __restrict__ out) {
    int b = blockIdx.x;
    int t = threadIdx.x;
    __shared__ unsigned sdiag[TOPK];
    __shared__ unsigned char sflag[TOPK];
    __shared__ int sslot[TOPK];
    __shared__ unsigned srows[256][32];
    __shared__ unsigned sremv[32];
    __shared__ unsigned skeepw[32];
    __shared__ int scount;
    if (t == 0) scount = 0;
    if (t < 32) sremv[t] = 0;
    __syncthreads();

    {
        int r = t;
        unsigned v[32];
#pragma unroll
        for (int w = 0; w < 32; w++) v[w] = g_mask[b][w][r];
        int wd = r >> 5;
        unsigned above = ~((2u << (r & 31)) - 1u);
        unsigned dg = v[wd] & above;
        sdiag[r] = dg;
        unsigned hi = 0;
#pragma unroll
        for (int w = 0; w < 32; w++)
            if (w > wd) hi |= v[w];
        bool flag = (dg != 0u) || (hi != 0u);
        sflag[r] = (unsigned char)flag;
        int slot = -2;
        if (flag) {
            slot = atomicAdd(&scount, 1);
            if (slot < 256) {
#pragma unroll
                for (int w = 0; w < 32; w++) srows[slot][w] = v[w];
            } else slot = -2;
        }
        sslot[r] = slot;
    }
    __syncthreads();

    if (t < 32) {
        int lane = t;
        for (int ch = 0; ch < 32; ch++) {
            unsigned cur = sremv[ch];
            int r = ch * 32 + lane;
            unsigned mym = sdiag[r];
            unsigned intra = __reduce_or_sync(0xffffffffu, mym);
            unsigned keepbits;
            if (intra == 0u) {
                keepbits = ~cur;
            } else {
                unsigned supp = cur;
                keepbits = 0u;
                for (int q = 0; q < 32; q++) {
                    unsigned m = __shfl_sync(0xffffffffu, mym, q);
                    if (!((supp >> q) & 1u)) { keepbits |= (1u << q); supp |= m; }
                }
            }
            if (lane == 0) skeepw[ch] = keepbits;
            bool mykeep = (keepbits >> lane) & 1u;
            unsigned todo = __ballot_sync(0xffffffffu, mykeep && sflag[r]);
            while (todo) {
                int q = __ffs(todo) - 1;
                todo &= todo - 1;
                int rr = ch * 32 + q;
                int slot = sslot[rr];
                unsigned v = (slot >= 0) ? srows[slot][lane] : g_mask[b][lane][rr];
                sremv[lane] |= v;
            }
            __syncwarp();
        }
    }
    __syncthreads();

    {
        int r = t;
        float kp = ((skeepw[r >> 5] >> (r & 31)) & 1u) ? 1.f : 0.f;
#pragma unroll
        for (int c = 0; c < 8; c++)
            out[((size_t)b * TOPK + r) * 8 + c] = g_top[b][r][c] * kp;
        out[(size_t)NB * TOPK * 8 + (size_t)b * TOPK + r] = 0.f;
        out[(size_t)NB * TOPK * 8 + (size_t)NB * TOPK + (size_t)b * TOPK + r] = kp;
    }
}

// ---------------- launch ----------------
extern "C" void kernel_launch(void* const* d_in, const int* in_sizes, int n_in,
                              void* d_out, int out_size) {
    const float* feat = (const float*)d_in[0];
    const int*   bidx = (const int*)d_in[1];
    const int*   coor = (const int*)d_in[2];
    const float* Wc   = (const float*)d_in[3];
    const float* bc   = (const float*)d_in[4];
    const float* Wr   = (const float*)d_in[5];
    const float* br   = (const float*)d_in[6];
    float* out = (float*)d_out;
    int N = in_sizes[0] / 256;

    k_zero<<<64, 256>>>();
    k_score<<<2048, 256>>>(feat, bidx, Wc, bc, Wr, br, N);
    k_thresh<<<NB, 1024>>>();
    k_compact<<<(N + 255) / 256, 256>>>(bidx, N);
    k_sort<<<NB, 1024>>>();
    k_decode<<<512, 256>>>(feat, coor, Wr, br, N);
    dim3 ge(NB, 32);
    k_iou<<<ge, 256>>>();
    k_nms_out<<<NB, 1024>>>(out);
}

// round 4
// speedup vs baseline: 2.5713x; 1.0467x over previous
#include <cuda_runtime.h>
#include <math.h>
#include <stdint.h>

#define NMAX 200000
#define NB 4
#define TOPK 1024
#define HBINS 2048
#define CAP 4096
#define THR 0.1f
#define NBLK 128
#define NTHR 1024
#define FULL 0xffffffffu

// ---------------- device scratch ----------------
__device__ float g_score[NMAX];
__device__ int   g_hist[NB][HBINS];            // zeroed at end of each run (P6)
__device__ int   g_cnt[NB];                    // zeroed at end of sort phase
__device__ unsigned long long g_cand[NB][CAP];
__device__ unsigned long long g_sel[NB][TOPK];
__device__ float g_nms[NB][TOPK][5];
__device__ float g_top[NB][TOPK][8];
__device__ unsigned g_mask[NB][32][TOPK];
__device__ int g_bar_count;
__device__ volatile int g_bar_gen;

// ---------------- kernel A: score-only GEMV (bit-exact), depth-2 prefetch ----------------
__global__ __launch_bounds__(256) void k_score(
    const float* __restrict__ feat,
    const float* __restrict__ Wc, const float* __restrict__ bc,
    const float* __restrict__ Wr, const float* __restrict__ br, int N)
{
    int lane = threadIdx.x & 31;
    int warp = blockIdx.x * (blockDim.x >> 5) + (threadIdx.x >> 5);
    int nwarps = gridDim.x * (blockDim.x >> 5);

    float wc0[8], wc1[8], ws8[8];
#pragma unroll
    for (int k = 0; k < 8; k++) {
        int c = lane * 8 + k;
        wc0[k] = Wc[c * 2 + 0];
        wc1[k] = Wc[c * 2 + 1];
        ws8[k] = Wr[c * 9 + 8];
    }
    float bc0 = bc[0], bc1 = bc[1];
    float br8 = br[8];

    int p = warp;
    float4 c0, c1, n0, n1;
    if (p < N) {
        const float4* fp = (const float4*)(feat + (size_t)p * 256 + lane * 8);
        c0 = fp[0]; c1 = fp[1];
    }
    if (p + nwarps < N) {
        const float4* fp = (const float4*)(feat + (size_t)(p + nwarps) * 256 + lane * 8);
        n0 = fp[0]; n1 = fp[1];
    }
    while (p < N) {
        int p2 = p + 2 * nwarps;
        float4 q0, q1;
        if (p2 < N) {
            const float4* fp = (const float4*)(feat + (size_t)p2 * 256 + lane * 8);
            q0 = fp[0]; q1 = fp[1];
        }
        float fv[8] = {c0.x, c0.y, c0.z, c0.w, c1.x, c1.y, c1.z, c1.w};
        float a0 = 0.f, a1 = 0.f, a10 = 0.f;
#pragma unroll
        for (int k = 0; k < 8; k++) {
            a0 = fmaf(fv[k], wc0[k], a0);
            a1 = fmaf(fv[k], wc1[k], a1);
            a10 = fmaf(fv[k], ws8[k], a10);
        }
#pragma unroll
        for (int off = 16; off > 0; off >>= 1) {
            a0 += __shfl_xor_sync(FULL, a0, off);
            a1 += __shfl_xor_sync(FULL, a1, off);
            a10 += __shfl_xor_sync(FULL, a10, off);
        }
        if (lane == 0) {
            float l0 = a0 + bc0, l1 = a1 + bc1;
            float conf = 1.f / (1.f + expf(l0 - l1));
            float s8 = a10 + br8;
            float scr = 1.f / (1.f + expf(-s8));
            g_score[p] = conf * scr;
        }
        c0 = n0; c1 = n1; n0 = q0; n1 = q1;
        p += nwarps;
    }
}

// ---------------- fused tail kernel ----------------
struct SmemU {
    union {
        int hist[NB][HBINS];                                    // 32KB  P1
        unsigned long long sk[CAP];                             // 32KB  P4
        float wsm[9 * 264];                                     // 9.3KB P5
        struct { float sx1[TOPK], sx2[TOPK], sy1[TOPK], sy2[TOPK], sa[TOPK]; } iou;
        struct {
            unsigned sdiag[TOPK];
            int sslot[TOPK];
            unsigned srows[256][32];
            unsigned char sflag[TOPK];
            unsigned sremv[32];
            unsigned skeepw[32];
            int scount;
        } nms;                                                  // ~41.3KB P7
    } u;
    int sthr[NB];
};

__device__ __forceinline__ void gridbar() {
    __syncthreads();
    if (threadIdx.x == 0) {
        __threadfence();
        int gen = g_bar_gen;
        if (atomicAdd(&g_bar_count, 1) == NBLK - 1) {
            g_bar_count = 0;
            __threadfence();
            g_bar_gen = gen + 1;
        } else {
            while (g_bar_gen == gen) { __nanosleep(64); }
        }
        __threadfence();
    }
    __syncthreads();
}

__global__ __launch_bounds__(NTHR, 1) void k_tail(
    const float* __restrict__ feat, const int* __restrict__ bidx,
    const int* __restrict__ coor, const float* __restrict__ Wr,
    const float* __restrict__ br, float* __restrict__ out, int N)
{
    __shared__ SmemU sm;
    int tid = threadIdx.x;
    int lane = tid & 31;
    int wid = tid >> 5;

    // ---- P1: histogram (smem) + merge (g_hist pre-zeroed by previous run) ----
    for (int i = tid; i < NB * HBINS; i += NTHR) ((int*)sm.u.hist)[i] = 0;
    __syncthreads();
    for (int p = blockIdx.x * NTHR + tid; p < N; p += NBLK * NTHR) {
        float s = g_score[p];
        int b = bidx[p];
        int bin = (int)(s * (float)HBINS);
        bin = max(0, min(HBINS - 1, bin));
        atomicAdd(&sm.u.hist[b][bin], 1);
    }
    __syncthreads();
    for (int i = tid; i < NB * HBINS; i += NTHR) {
        int v = ((int*)sm.u.hist)[i];
        if (v) atomicAdd(&((int*)g_hist)[i], v);
    }
    gridbar();  // BAR1

    // ---- P2: threshold (warps 0..3, redundant per block) ----
    if (wid < NB) {
        int b = wid;
        int total = 0, T = 0;
        bool found = false;
        for (int c = (HBINS / 32) - 1; c >= 0 && !found; c--) {
            int v = g_hist[b][c * 32 + lane];
            int s = v;
#pragma unroll
            for (int off = 1; off < 32; off <<= 1) {
                int o = __shfl_down_sync(FULL, s, off);
                if (lane + off < 32) s += o;
            }
            int cum = total + s;
            unsigned m = __ballot_sync(FULL, cum >= TOPK);
            if (m) {
                T = c * 32 + (31 - __clz(m));
                found = true;
            } else {
                total += __shfl_sync(FULL, s, 0);
            }
        }
        if (lane == 0) sm.sthr[b] = T;
    }
    __syncthreads();

    // ---- P3: compact (warp-aggregated) ----
    for (int p = blockIdx.x * NTHR + tid; ; p += NBLK * NTHR) {
        bool live = p < N;
        if (!__ballot_sync(FULL, live)) break;
        bool pass = false;
        int b = 0;
        unsigned long long key = 0ull;
        if (live) {
            float s = g_score[p];
            b = bidx[p];
            int bin = (int)(s * (float)HBINS);
            bin = max(0, min(HBINS - 1, bin));
            pass = bin >= sm.sthr[b];
            key = ((unsigned long long)__float_as_uint(s) << 32) | (unsigned)(~(unsigned)p);
        }
#pragma unroll
        for (int bb = 0; bb < NB; bb++) {
            unsigned m = __ballot_sync(FULL, pass && b == bb);
            if (m) {
                int leader = __ffs(m) - 1;
                int base = 0;
                if (lane == leader) base = atomicAdd(&g_cnt[bb], __popc(m));
                base = __shfl_sync(FULL, base, leader);
                if (pass && b == bb) {
                    int pos = base + __popc(m & ((1u << lane) - 1u));
                    if (pos < CAP) g_cand[bb][pos] = key;
                }
            }
        }
    }
    gridbar();  // BAR2

    // ---- P4: bitonic sort (blocks 0..3) ----
    if (blockIdx.x < NB) {
        int b = blockIdx.x;
        int cnt = min(g_cnt[b], CAP);
        int size = TOPK;
        while (size < cnt) size <<= 1;
        for (int i = tid; i < size; i += NTHR)
            sm.u.sk[i] = (i < cnt) ? g_cand[b][i] : 0ull;
        __syncthreads();
        for (unsigned kk = 2; kk <= (unsigned)size; kk <<= 1)
            for (unsigned j = kk >> 1; j > 0; j >>= 1) {
                for (unsigned i = tid; i < (unsigned)size; i += NTHR) {
                    unsigned ixj = i ^ j;
                    if (ixj > i) {
                        unsigned long long a = sm.u.sk[i], c = sm.u.sk[ixj];
                        bool desc = ((i & kk) == 0);
                        if (desc ? (a < c) : (a > c)) { sm.u.sk[i] = c; sm.u.sk[ixj] = a; }
                    }
                }
                __syncthreads();
            }
        if (tid < TOPK) g_sel[b][tid] = sm.u.sk[tid];
        __syncthreads();
        if (tid == 0) g_cnt[b] = 0;   // re-zero for next replay
    }
    gridbar();  // BAR3

    // ---- P5: decode selected boxes (warp per selection; weights in smem, swizzled) ----
    for (int i = tid; i < 9 * 256; i += NTHR) {
        int o = i >> 8, f = i & 255;
        sm.u.wsm[o * 264 + f + (f >> 5)] = Wr[f * 9 + o];
    }
    __syncthreads();
    {
        int idx = blockIdx.x * 32 + wid;     // 0..4095
        int b = idx >> 10, t = idx & (TOPK - 1);
        unsigned long long key = g_sel[b][t];
        unsigned p = ~(unsigned)(key & 0xffffffffu);
        float score = __uint_as_float((unsigned)(key >> 32));
        bool valid = (key != 0ull) && (p < (unsigned)N);
        float bx[7];
        if (valid) {
            const float4* fp = (const float4*)(feat + (size_t)p * 256 + lane * 8);
            float4 f0 = fp[0], f1 = fp[1];
            float fv[8] = {f0.x, f0.y, f0.z, f0.w, f1.x, f1.y, f1.z, f1.w};
            float acc[9];
#pragma unroll
            for (int o = 0; o < 9; o++) acc[o] = 0.f;
#pragma unroll
            for (int o = 0; o < 9; o++)
#pragma unroll
                for (int k = 0; k < 8; k++) {
                    int f = 8 * lane + k;
                    float wv = sm.u.wsm[o * 264 + f + (f >> 5)];
                    acc[o] = fmaf(fv[k], wv, acc[o]);
                }
#pragma unroll
            for (int off = 16; off > 0; off >>= 1)
#pragma unroll
                for (int o = 0; o < 9; o++)
                    acc[o] += __shfl_xor_sync(FULL, acc[o], off);
            float r0 = acc[0] + br[0], r1 = acc[1] + br[1], r2 = acc[2] + br[2];
            float d0 = acc[3] + br[3], d1 = acc[4] + br[4], d2 = acc[5] + br[5];
            float a0 = acc[6] + br[6], a1 = acc[7] + br[7];
            int cx = coor[p * 2 + 0], cy = coor[p * 2 + 1];
            bx[0] = (float)cx * 0.8f + r0;
            bx[1] = (float)cy * 0.8f + r1;
            bx[2] = r2;
            bx[3] = expf(fminf(fmaxf(d0, -6.f), 6.f));
            bx[4] = expf(fminf(fmaxf(d1, -6.f), 6.f));
            bx[5] = expf(fminf(fmaxf(d2, -6.f), 6.f));
            bx[6] = atan2f(a0, a1);
        } else {
#pragma unroll
            for (int c = 0; c < 7; c++) bx[c] = 0.f;
            score = 0.f;
        }
        if (lane == 0) {
#pragma unroll
            for (int c = 0; c < 7; c++) g_top[b][t][c] = bx[c];
            g_top[b][t][7] = score;
            float x = bx[0], y = bx[1], l = bx[3], w = bx[4];
            g_nms[b][t][0] = x - l * 0.5f;
            g_nms[b][t][1] = x + l * 0.5f;
            g_nms[b][t][2] = y - w * 0.5f;
            g_nms[b][t][3] = y + w * 0.5f;
            g_nms[b][t][4] = l * w;
        }
    }
    gridbar();  // BAR4

    // ---- P6: IoU bitmask (block -> (b, rowgroup)); also re-zero g_hist ----
    {
        int b = blockIdx.x >> 5, rg = blockIdx.x & 31;
        for (int i = tid; i < TOPK; i += NTHR) {
            sm.u.iou.sx1[i] = g_nms[b][i][0];
            sm.u.iou.sx2[i] = g_nms[b][i][1];
            sm.u.iou.sy1[i] = g_nms[b][i][2];
            sm.u.iou.sy2[i] = g_nms[b][i][3];
            sm.u.iou.sa[i]  = g_nms[b][i][4];
        }
        __syncthreads();
        int col = tid, wp = tid >> 5;
        float cx1 = sm.u.iou.sx1[col], cx2 = sm.u.iou.sx2[col];
        float cy1 = sm.u.iou.sy1[col], cy2 = sm.u.iou.sy2[col], ca = sm.u.iou.sa[col];
        for (int rr = 0; rr < 32; rr++) {
            int r = rg * 32 + rr;
            float rx1 = sm.u.iou.sx1[r], rx2 = sm.u.iou.sx2[r];
            float ry1 = sm.u.iou.sy1[r], ry2 = sm.u.iou.sy2[r], ra = sm.u.iou.sa[r];
            float ix = fmaxf(fminf(rx2, cx2) - fmaxf(rx1, cx1), 0.f);
            float iy = fmaxf(fminf(ry2, cy2) - fmaxf(ry1, cy1), 0.f);
            float inter = ix * iy;
            float uni = fmaxf(ra + ca - inter, 1e-6f);
            bool sup = inter > THR * uni;
            unsigned bal = __ballot_sync(FULL, sup);
            if (lane == 0) g_mask[b][wp][r] = bal;
        }
        // re-zero g_hist slice for next replay (64 ints per block)
        if (tid < 64) ((int*)g_hist)[blockIdx.x * 64 + tid] = 0;
    }
    gridbar();  // BAR5

    // ---- P7: sequential NMS + output (blocks 0..3) ----
    if (blockIdx.x >= NB) return;
    {
        int b = blockIdx.x;
        int t = tid;
        if (t == 0) sm.u.nms.scount = 0;
        if (t < 32) sm.u.nms.sremv[t] = 0;
        __syncthreads();
        {
            int r = t;
            unsigned v[32];
#pragma unroll
            for (int w = 0; w < 32; w++) v[w] = g_mask[b][w][r];
            int wd = r >> 5;
            unsigned above = ~((2u << (r & 31)) - 1u);
            unsigned dg = v[wd] & above;
            sm.u.nms.sdiag[r] = dg;
            unsigned hi = 0;
#pragma unroll
            for (int w = 0; w < 32; w++)
                if (w > wd) hi |= v[w];
            bool flag = (dg != 0u) || (hi != 0u);
            sm.u.nms.sflag[r] = (unsigned char)flag;
            int slot = -2;
            if (flag) {
                slot = atomicAdd(&sm.u.nms.scount, 1);
                if (slot < 256) {
#pragma unroll
                    for (int w = 0; w < 32; w++) sm.u.nms.srows[slot][w] = v[w];
                } else slot = -2;
            }
            sm.u.nms.sslot[r] = slot;
        }
        __syncthreads();

        if (t < 32) {
            int ln = t;
            for (int ch = 0; ch < 32; ch++) {
                unsigned cur = sm.u.nms.sremv[ch];
                int r = ch * 32 + ln;
                unsigned mym = sm.u.nms.sdiag[r];
                unsigned intra = __reduce_or_sync(FULL, mym);
                unsigned keepbits;
                if (intra == 0u) {
                    keepbits = ~cur;
                } else {
                    unsigned supp = cur;
                    keepbits = 0u;
                    for (int q = 0; q < 32; q++) {
                        unsigned m = __shfl_sync(FULL, mym, q);
                        if (!((supp >> q) & 1u)) { keepbits |= (1u << q); supp |= m; }
                    }
                }
                if (ln == 0) sm.u.nms.skeepw[ch] = keepbits;
                bool mykeep = (keepbits >> ln) & 1u;
                unsigned todo = __ballot_sync(FULL, mykeep && sm.u.nms.sflag[r]);
                while (todo) {
                    int q = __ffs(todo) - 1;
                    todo &= todo - 1;
                    int rr = ch * 32 + q;
                    int slot = sm.u.nms.sslot[rr];
                    unsigned v = (slot >= 0) ? sm.u.nms.srows[slot][ln] : g_mask[b][ln][rr];
                    sm.u.nms.sremv[ln] |= v;
                }
                __syncwarp();
            }
        }
        __syncthreads();

        {
            int r = t;
            float kp = ((sm.u.nms.skeepw[r >> 5] >> (r & 31)) & 1u) ? 1.f : 0.f;
#pragma unroll
            for (int c = 0; c < 8; c++)
                out[((size_t)b * TOPK + r) * 8 + c] = g_top[b][r][c] * kp;
            out[(size_t)NB * TOPK * 8 + (size_t)b * TOPK + r] = 0.f;
            out[(size_t)NB * TOPK * 8 + (size_t)NB * TOPK + (size_t)b * TOPK + r] = kp;
        }
    }
}

// ---------------- launch ----------------
extern "C" void kernel_launch(void* const* d_in, const int* in_sizes, int n_in,
                              void* d_out, int out_size) {
    const float* feat = (const float*)d_in[0];
    const int*   bidx = (const int*)d_in[1];
    const int*   coor = (const int*)d_in[2];
    const float* Wc   = (const float*)d_in[3];
    const float* bc   = (const float*)d_in[4];
    const float* Wr   = (const float*)d_in[5];
    const float* br   = (const float*)d_in[6];
    float* out = (float*)d_out;
    int N = in_sizes[0] / 256;

    k_score<<<2048, 256>>>(feat, Wc, bc, Wr, br, N);
    k_tail<<<NBLK, NTHR>>>(feat, bidx, coor, Wr, br, out, N);
}

// round 5
// speedup vs baseline: 3.3082x; 1.2866x over previous
#include <cuda_runtime.h>
#include <math.h>
#include <stdint.h>

#define NMAX 200000
#define NB 4
#define TOPK 1024
#define HBINS 8192
#define CAP 4096
#define THR 0.1f
#define NBLK 128
#define NTHR 1024
#define FULL 0xffffffffu

// ---------------- device scratch ----------------
__device__ float g_score[NMAX];
__device__ int   g_hist[NB][HBINS];            // re-zeroed in P6 each run
__device__ int   g_cnt[NB];                    // re-zeroed in P5 each run
__device__ unsigned long long g_cand[NB][CAP];
__device__ unsigned long long g_sel[NB][TOPK];
__device__ float g_nms[NB][TOPK][5];
__device__ float g_top[NB][TOPK][8];
__device__ unsigned g_mask[NB][32][TOPK];
__device__ int g_bar_count;
__device__ volatile int g_bar_gen;

// ---------------- kernel A: score-only GEMV (bit-exact), depth-3 prefetch ----------------
__global__ __launch_bounds__(256) void k_score(
    const float* __restrict__ feat,
    const float* __restrict__ Wc, const float* __restrict__ bc,
    const float* __restrict__ Wr, const float* __restrict__ br, int N)
{
    int lane = threadIdx.x & 31;
    int warp = blockIdx.x * (blockDim.x >> 5) + (threadIdx.x >> 5);
    int nwarps = gridDim.x * (blockDim.x >> 5);

    float wc0[8], wc1[8], ws8[8];
#pragma unroll
    for (int k = 0; k < 8; k++) {
        int c = lane * 8 + k;
        wc0[k] = Wc[c * 2 + 0];
        wc1[k] = Wc[c * 2 + 1];
        ws8[k] = Wr[c * 9 + 8];
    }
    float bc0 = bc[0], bc1 = bc[1];
    float br8 = br[8];

    int p = warp;
    float4 s0a, s0b, s1a, s1b, s2a, s2b;
    if (p < N) {
        const float4* fp = (const float4*)(feat + (size_t)p * 256 + lane * 8);
        s0a = fp[0]; s0b = fp[1];
    }
    if (p + nwarps < N) {
        const float4* fp = (const float4*)(feat + (size_t)(p + nwarps) * 256 + lane * 8);
        s1a = fp[0]; s1b = fp[1];
    }
    if (p + 2 * nwarps < N) {
        const float4* fp = (const float4*)(feat + (size_t)(p + 2 * nwarps) * 256 + lane * 8);
        s2a = fp[0]; s2b = fp[1];
    }
    while (p < N) {
        int p3 = p + 3 * nwarps;
        float4 t0, t1;
        if (p3 < N) {
            const float4* fp = (const float4*)(feat + (size_t)p3 * 256 + lane * 8);
            t0 = fp[0]; t1 = fp[1];
        }
        float fv[8] = {s0a.x, s0a.y, s0a.z, s0a.w, s0b.x, s0b.y, s0b.z, s0b.w};
        float a0 = 0.f, a1 = 0.f, a10 = 0.f;
#pragma unroll
        for (int k = 0; k < 8; k++) {
            a0 = fmaf(fv[k], wc0[k], a0);
            a1 = fmaf(fv[k], wc1[k], a1);
            a10 = fmaf(fv[k], ws8[k], a10);
        }
#pragma unroll
        for (int off = 16; off > 0; off >>= 1) {
            a0 += __shfl_xor_sync(FULL, a0, off);
            a1 += __shfl_xor_sync(FULL, a1, off);
            a10 += __shfl_xor_sync(FULL, a10, off);
        }
        if (lane == 0) {
            float l0 = a0 + bc0, l1 = a1 + bc1;
            float conf = 1.f / (1.f + expf(l0 - l1));
            float s8 = a10 + br8;
            float scr = 1.f / (1.f + expf(-s8));
            g_score[p] = conf * scr;
        }
        s0a = s1a; s0b = s1b; s1a = s2a; s1b = s2b; s2a = t0; s2b = t1;
        p += nwarps;
    }
}

// ---------------- fused tail kernel ----------------
struct SmemU {
    union {
        unsigned long long sk[CAP];                             // 32KB  P4 rank
        float wsm[9 * 264];                                     // 9.3KB P5
        struct { float sx1[TOPK], sx2[TOPK], sy1[TOPK], sy2[TOPK], sa[TOPK]; } iou;
        struct {
            unsigned sdiag[TOPK];
            int sslot[TOPK];
            unsigned srows[256][32];
            unsigned char sflag[TOPK];
            unsigned sremv[32];
            unsigned skeepw[32];
            int scount;
        } nms;                                                  // ~41.3KB P7
    } u;
    int sthr[NB];
};

__device__ __forceinline__ void gridbar() {
    __syncthreads();
    if (threadIdx.x == 0) {
        __threadfence();
        int gen = g_bar_gen;
        if (atomicAdd(&g_bar_count, 1) == NBLK - 1) {
            g_bar_count = 0;
            __threadfence();
            g_bar_gen = gen + 1;
        } else {
            while (g_bar_gen == gen) { __nanosleep(64); }
        }
        __threadfence();
    }
    __syncthreads();
}

__global__ __launch_bounds__(NTHR, 1) void k_tail(
    const float* __restrict__ feat, const int* __restrict__ bidx,
    const int* __restrict__ coor, const float* __restrict__ Wr,
    const float* __restrict__ br, float* __restrict__ out, int N)
{
    __shared__ SmemU sm;
    int tid = threadIdx.x;
    int lane = tid & 31;
    int wid = tid >> 5;

    // ---- P1: histogram, direct global atomics (g_hist pre-zeroed by previous run) ----
    for (int p = blockIdx.x * NTHR + tid; p < N; p += NBLK * NTHR) {
        float s = g_score[p];
        int b = bidx[p];
        int bin = (int)(s * (float)HBINS);
        bin = max(0, min(HBINS - 1, bin));
        atomicAdd(&g_hist[b][bin], 1);
    }
    gridbar();  // BAR1

    // ---- P2: threshold, two-level suffix scan (warps 0..3, redundant per block) ----
    if (wid < NB) {
        int b = wid;
        const int SEG = HBINS / 32;   // 256
        const int SUB = SEG / 32;     // 8
        int s = 0;
        {
            const int4* hp = (const int4*)&g_hist[b][lane * SEG];
#pragma unroll
            for (int i = 0; i < SEG / 4; i++) {
                int4 v = hp[i];
                s += v.x + v.y + v.z + v.w;
            }
        }
        int suf = s;
#pragma unroll
        for (int off = 1; off < 32; off <<= 1) {
            int o = __shfl_down_sync(FULL, suf, off);
            if (lane + off < 32) suf += o;
        }
        unsigned m = __ballot_sync(FULL, suf >= TOPK);
        int T = 0;
        if (m) {
            int lstar = 31 - __clz(m);
            int sufn = __shfl_down_sync(FULL, suf, 1);
            int myabove = (lane == 31) ? 0 : sufn;
            int above = __shfl_sync(FULL, myabove, lstar);
            int b0 = lstar * SEG;
            int s2 = 0;
#pragma unroll
            for (int i = 0; i < SUB; i++) s2 += g_hist[b][b0 + lane * SUB + i];
            int suf2 = s2;
#pragma unroll
            for (int off = 1; off < 32; off <<= 1) {
                int o = __shfl_down_sync(FULL, suf2, off);
                if (lane + off < 32) suf2 += o;
            }
            unsigned m2 = __ballot_sync(FULL, above + suf2 >= TOPK);
            int l2 = 31 - __clz(m2);
            int sufn2 = __shfl_down_sync(FULL, suf2, 1);
            int myabove2 = (lane == 31) ? 0 : sufn2;
            int above2 = above + __shfl_sync(FULL, myabove2, l2);
            int Tl = 0;
            if (lane == l2) {
                int acc = above2;
                for (int bin = b0 + l2 * SUB + SUB - 1; bin >= b0 + l2 * SUB; bin--) {
                    acc += g_hist[b][bin];
                    if (acc >= TOPK) { Tl = bin; break; }
                }
            }
            T = __shfl_sync(FULL, Tl, l2);
        }
        if (lane == 0) sm.sthr[b] = T;
    }
    __syncthreads();

    // ---- P3: compact (warp-aggregated) ----
    for (int p = blockIdx.x * NTHR + tid; ; p += NBLK * NTHR) {
        bool live = p < N;
        if (!__ballot_sync(FULL, live)) break;
        bool pass = false;
        int b = 0;
        unsigned long long key = 0ull;
        if (live) {
            float s = g_score[p];
            b = bidx[p];
            int bin = (int)(s * (float)HBINS);
            bin = max(0, min(HBINS - 1, bin));
            pass = bin >= sm.sthr[b];
            key = ((unsigned long long)__float_as_uint(s) << 32) | (unsigned)(~(unsigned)p);
        }
#pragma unroll
        for (int bb = 0; bb < NB; bb++) {
            unsigned m = __ballot_sync(FULL, pass && b == bb);
            if (m) {
                int leader = __ffs(m) - 1;
                int base = 0;
                if (lane == leader) base = atomicAdd(&g_cnt[bb], __popc(m));
                base = __shfl_sync(FULL, base, leader);
                if (pass && b == bb) {
                    int pos = base + __popc(m & ((1u << lane) - 1u));
                    if (pos < CAP) g_cand[bb][pos] = key;
                }
            }
        }
    }
    gridbar();  // BAR2

    // ---- P4: rank-and-scatter top-K (32 blocks per batch, warp per candidate) ----
    {
        int b = blockIdx.x >> 5, chunk = blockIdx.x & 31;
        int cnt = min(g_cnt[b], CAP);
        for (int i = tid; i < cnt; i += NTHR) sm.u.sk[i] = g_cand[b][i];
        __syncthreads();
        for (int i = chunk * 32 + wid; i < cnt; i += 1024) {
            unsigned long long key = sm.u.sk[i];
            unsigned c = 0;
            for (int j = lane; j < cnt; j += 32)
                c += (sm.u.sk[j] > key) ? 1u : 0u;
            unsigned r = __reduce_add_sync(FULL, c);
            if (r < TOPK) g_sel[b][r] = key;
        }
    }
    gridbar();  // BAR3

    // ---- P5: decode selected boxes (warp per selection; weights in smem, swizzled) ----
    for (int i = tid; i < 9 * 256; i += NTHR) {
        int o = i >> 8, f = i & 255;
        sm.u.wsm[o * 264 + f + (f >> 5)] = Wr[f * 9 + o];
    }
    if (tid == 0 && blockIdx.x < NB) g_cnt[blockIdx.x] = 0;  // re-zero for next replay
    __syncthreads();
    {
        int idx = blockIdx.x * 32 + wid;     // 0..4095
        int b = idx >> 10, t = idx & (TOPK - 1);
        unsigned long long key = g_sel[b][t];
        unsigned p = ~(unsigned)(key & 0xffffffffu);
        float score = __uint_as_float((unsigned)(key >> 32));
        bool valid = (key != 0ull) && (p < (unsigned)N);
        float bx[7];
        if (valid) {
            const float4* fp = (const float4*)(feat + (size_t)p * 256 + lane * 8);
            float4 f0 = fp[0], f1 = fp[1];
            float fv[8] = {f0.x, f0.y, f0.z, f0.w, f1.x, f1.y, f1.z, f1.w};
            float acc[9];
#pragma unroll
            for (int o = 0; o < 9; o++) acc[o] = 0.f;
#pragma unroll
            for (int o = 0; o < 9; o++)
#pragma unroll
                for (int k = 0; k < 8; k++) {
                    int f = 8 * lane + k;
                    float wv = sm.u.wsm[o * 264 + f + (f >> 5)];
                    acc[o] = fmaf(fv[k], wv, acc[o]);
                }
#pragma unroll
            for (int off = 16; off > 0; off >>= 1)
#pragma unroll
                for (int o = 0; o < 9; o++)
                    acc[o] += __shfl_xor_sync(FULL, acc[o], off);
            float r0 = acc[0] + br[0], r1 = acc[1] + br[1], r2 = acc[2] + br[2];
            float d0 = acc[3] + br[3], d1 = acc[4] + br[4], d2 = acc[5] + br[5];
            float a0 = acc[6] + br[6], a1 = acc[7] + br[7];
            int cx = coor[p * 2 + 0], cy = coor[p * 2 + 1];
            bx[0] = (float)cx * 0.8f + r0;
            bx[1] = (float)cy * 0.8f + r1;
            bx[2] = r2;
            bx[3] = expf(fminf(fmaxf(d0, -6.f), 6.f));
            bx[4] = expf(fminf(fmaxf(d1, -6.f), 6.f));
            bx[5] = expf(fminf(fmaxf(d2, -6.f), 6.f));
            bx[6] = atan2f(a0, a1);
        } else {
#pragma unroll
            for (int c = 0; c < 7; c++) bx[c] = 0.f;
            score = 0.f;
        }
        if (lane == 0) {
#pragma unroll
            for (int c = 0; c < 7; c++) g_top[b][t][c] = bx[c];
            g_top[b][t][7] = score;
            float x = bx[0], y = bx[1], l = bx[3], w = bx[4];
            g_nms[b][t][0] = x - l * 0.5f;
            g_nms[b][t][1] = x + l * 0.5f;
            g_nms[b][t][2] = y - w * 0.5f;
            g_nms[b][t][3] = y + w * 0.5f;
            g_nms[b][t][4] = l * w;
        }
    }
    gridbar();  // BAR4

    // ---- P6: IoU bitmask; also re-zero g_hist ----
    {
        int b = blockIdx.x >> 5, rg = blockIdx.x & 31;
        for (int i = tid; i < TOPK; i += NTHR) {
            sm.u.iou.sx1[i] = g_nms[b][i][0];
            sm.u.iou.sx2[i] = g_nms[b][i][1];
            sm.u.iou.sy1[i] = g_nms[b][i][2];
            sm.u.iou.sy2[i] = g_nms[b][i][3];
            sm.u.iou.sa[i]  = g_nms[b][i][4];
        }
        __syncthreads();
        int col = tid, wp = tid >> 5;
        float cx1 = sm.u.iou.sx1[col], cx2 = sm.u.iou.sx2[col];
        float cy1 = sm.u.iou.sy1[col], cy2 = sm.u.iou.sy2[col], ca = sm.u.iou.sa[col];
        for (int rr = 0; rr < 32; rr++) {
            int r = rg * 32 + rr;
            float rx1 = sm.u.iou.sx1[r], rx2 = sm.u.iou.sx2[r];
            float ry1 = sm.u.iou.sy1[r], ry2 = sm.u.iou.sy2[r], ra = sm.u.iou.sa[r];
            float ix = fmaxf(fminf(rx2, cx2) - fmaxf(rx1, cx1), 0.f);
            float iy = fmaxf(fminf(ry2, cy2) - fmaxf(ry1, cy1), 0.f);
            float inter = ix * iy;
            float uni = fmaxf(ra + ca - inter, 1e-6f);
            bool sup = inter > THR * uni;
            unsigned bal = __ballot_sync(FULL, sup);
            if (lane == 0) g_mask[b][wp][r] = bal;
        }
        // re-zero g_hist slice for next replay (NB*HBINS/NBLK = 256 ints per block)
        if (tid < 256) ((int*)g_hist)[blockIdx.x * 256 + tid] = 0;
    }
    gridbar();  // BAR5

    // ---- P7: sequential NMS + output (blocks 0..3) ----
    if (blockIdx.x >= NB) return;
    {
        int b = blockIdx.x;
        int t = tid;
        if (t == 0) sm.u.nms.scount = 0;
        if (t < 32) sm.u.nms.sremv[t] = 0;
        __syncthreads();
        {
            int r = t;
            unsigned v[32];
#pragma unroll
            for (int w = 0; w < 32; w++) v[w] = g_mask[b][w][r];
            int wd = r >> 5;
            unsigned above = ~((2u << (r & 31)) - 1u);
            unsigned dg = v[wd] & above;
            sm.u.nms.sdiag[r] = dg;
            unsigned hi = 0;
#pragma unroll
            for (int w = 0; w < 32; w++)
                if (w > wd) hi |= v[w];
            bool flag = (dg != 0u) || (hi != 0u);
            sm.u.nms.sflag[r] = (unsigned char)flag;
            int slot = -2;
            if (flag) {
                slot = atomicAdd(&sm.u.nms.scount, 1);
                if (slot < 256) {
#pragma unroll
                    for (int w = 0; w < 32; w++) sm.u.nms.srows[slot][w] = v[w];
                } else slot = -2;
            }
            sm.u.nms.sslot[r] = slot;
        }
        __syncthreads();

        if (t < 32) {
            int ln = t;
            for (int ch = 0; ch < 32; ch++) {
                unsigned cur = sm.u.nms.sremv[ch];
                int r = ch * 32 + ln;
                unsigned mym = sm.u.nms.sdiag[r];
                unsigned intra = __reduce_or_sync(FULL, mym);
                unsigned keepbits;
                if (intra == 0u) {
                    keepbits = ~cur;
                } else {
                    unsigned supp = cur;
                    keepbits = 0u;
                    for (int q = 0; q < 32; q++) {
                        unsigned m = __shfl_sync(FULL, mym, q);
                        if (!((supp >> q) & 1u)) { keepbits |= (1u << q); supp |= m; }
                    }
                }
                if (ln == 0) sm.u.nms.skeepw[ch] = keepbits;
                bool mykeep = (keepbits >> ln) & 1u;
                unsigned todo = __ballot_sync(FULL, mykeep && sm.u.nms.sflag[r]);
                while (todo) {
                    int q = __ffs(todo) - 1;
                    todo &= todo - 1;
                    int rr = ch * 32 + q;
                    int slot = sm.u.nms.sslot[rr];
                    unsigned v = (slot >= 0) ? sm.u.nms.srows[slot][ln] : g_mask[b][ln][rr];
                    sm.u.nms.sremv[ln] |= v;
                }
                __syncwarp();
            }
        }
        __syncthreads();

        {
            int r = t;
            float kp = ((sm.u.nms.skeepw[r >> 5] >> (r & 31)) & 1u) ? 1.f : 0.f;
#pragma unroll
            for (int c = 0; c < 8; c++)
                out[((size_t)b * TOPK + r) * 8 + c] = g_top[b][r][c] * kp;
            out[(size_t)NB * TOPK * 8 + (size_t)b * TOPK + r] = 0.f;
            out[(size_t)NB * TOPK * 8 + (size_t)NB * TOPK + (size_t)b * TOPK + r] = kp;
        }
    }
}

// ---------------- launch ----------------
extern "C" void kernel_launch(void* const* d_in, const int* in_sizes, int n_in,
                              void* d_out, int out_size) {
    const float* feat = (const float*)d_in[0];
    const int*   bidx = (const int*)d_in[1];
    const int*   coor = (const int*)d_in[2];
    const float* Wc   = (const float*)d_in[3];
    const float* bc   = (const float*)d_in[4];
    const float* Wr   = (const float*)d_in[5];
    const float* br   = (const float*)d_in[6];
    float* out = (float*)d_out;
    int N = in_sizes[0] / 256;

    k_score<<<2048, 256>>>(feat, Wc, bc, Wr, br, N);
    k_tail<<<NBLK, NTHR>>>(feat, bidx, coor, Wr, br, out, N);
}

// round 6
// speedup vs baseline: 3.5484x; 1.0726x over previous
#include <cuda_runtime.h>
#include <math.h>
#include <stdint.h>

#define NMAX 200000
#define NB 4
#define TOPK 1024
#define HBINS 8192
#define CAP 4096
#define THR 0.1f
#define GRID 148
#define NTHR 1024
#define FULL 0xffffffffu

// ---------------- device scratch ----------------
__device__ float g_score[NMAX];
__device__ int   g_hist[NB][HBINS];            // re-zeroed in P6 each run
__device__ int   g_cnt[NB];                    // re-zeroed in P5 each run
__device__ unsigned long long g_cand[NB][CAP];
__device__ unsigned long long g_sel[NB][TOPK];
__device__ float g_nms[NB][TOPK][5];
__device__ float g_top[NB][TOPK][8];
__device__ unsigned g_mask[NB][32][TOPK];
__device__ int g_bar_count;
__device__ volatile unsigned g_bar_gen;

struct SmemU {
    union {
        unsigned long long sk[CAP];                             // 32KB  P4 rank
        float wsm[9 * 264];                                     // 9.3KB P5
        struct { float sx1[TOPK], sx2[TOPK], sy1[TOPK], sy2[TOPK], sa[TOPK]; } iou;
        struct {
            unsigned sdiag[TOPK];
            int sslot[TOPK];
            unsigned srows[256][32];
            unsigned char sflag[TOPK];
            unsigned sremv[32];
            unsigned skeepw[32];
            int scount;
        } nms;                                                  // ~41.3KB P7
    } u;
    int sthr[NB];
};

__device__ __forceinline__ void gridbar() {
    __syncthreads();
    if (threadIdx.x == 0) {
        __threadfence();
        unsigned gen = g_bar_gen;
        if (atomicAdd(&g_bar_count, 1) == GRID - 1) {
            g_bar_count = 0;
            __threadfence();
            g_bar_gen = gen + 1u;
        } else {
            while (g_bar_gen == gen) { __nanosleep(64); }
        }
        __threadfence();
    }
    __syncthreads();
}

// ---------------- single fused persistent kernel ----------------
__global__ __launch_bounds__(NTHR, 1) void k_all(
    const float* __restrict__ feat, const int* __restrict__ bidx,
    const int* __restrict__ coor,
    const float* __restrict__ Wc, const float* __restrict__ bc,
    const float* __restrict__ Wr, const float* __restrict__ br,
    float* __restrict__ out, int N)
{
    __shared__ SmemU sm;
    int tid = threadIdx.x;
    int lane = tid & 31;
    int wid = tid >> 5;

    // ================ P0: score GEMV (bit-exact) + fused histogram ================
    {
        int warp = blockIdx.x * 32 + wid;
        int nwarps = GRID * 32;

        float wc0[8], wc1[8], ws8[8];
#pragma unroll
        for (int k = 0; k < 8; k++) {
            int c = lane * 8 + k;
            wc0[k] = Wc[c * 2 + 0];
            wc1[k] = Wc[c * 2 + 1];
            ws8[k] = Wr[c * 9 + 8];
        }
        float bc0 = bc[0], bc1 = bc[1];
        float br8 = br[8];

        int p = warp;
        float4 c0, c1, n0, n1;
        if (p < N) {
            const float4* fp = (const float4*)(feat + (size_t)p * 256 + lane * 8);
            c0 = fp[0]; c1 = fp[1];
        }
        if (p + nwarps < N) {
            const float4* fp = (const float4*)(feat + (size_t)(p + nwarps) * 256 + lane * 8);
            n0 = fp[0]; n1 = fp[1];
        }
        while (p < N) {
            int p2 = p + 2 * nwarps;
            float4 q0, q1;
            if (p2 < N) {
                const float4* fp = (const float4*)(feat + (size_t)p2 * 256 + lane * 8);
                q0 = fp[0]; q1 = fp[1];
            }
            float fv[8] = {c0.x, c0.y, c0.z, c0.w, c1.x, c1.y, c1.z, c1.w};
            float a0 = 0.f, a1 = 0.f, a10 = 0.f;
#pragma unroll
            for (int k = 0; k < 8; k++) {
                a0 = fmaf(fv[k], wc0[k], a0);
                a1 = fmaf(fv[k], wc1[k], a1);
                a10 = fmaf(fv[k], ws8[k], a10);
            }
#pragma unroll
            for (int off = 16; off > 0; off >>= 1) {
                a0 += __shfl_xor_sync(FULL, a0, off);
                a1 += __shfl_xor_sync(FULL, a1, off);
                a10 += __shfl_xor_sync(FULL, a10, off);
            }
            if (lane == 0) {
                float l0 = a0 + bc0, l1 = a1 + bc1;
                float conf = 1.f / (1.f + expf(l0 - l1));
                float s8 = a10 + br8;
                float scr = 1.f / (1.f + expf(-s8));
                float score = conf * scr;
                g_score[p] = score;
                int b = bidx[p];
                int bin = (int)(score * (float)HBINS);
                bin = max(0, min(HBINS - 1, bin));
                atomicAdd(&g_hist[b][bin], 1);
            }
            c0 = n0; c1 = n1; n0 = q0; n1 = q1;
            p += nwarps;
        }
    }
    gridbar();  // BAR1

    // ================ P2: threshold (warps 0..3, redundant per block) ================
    if (wid < NB) {
        int b = wid;
        const int SEG = HBINS / 32;   // 256
        const int SUB = SEG / 32;     // 8
        int s = 0;
        {
            const int4* hp = (const int4*)&g_hist[b][lane * SEG];
#pragma unroll
            for (int i = 0; i < SEG / 4; i++) {
                int4 v = hp[i];
                s += v.x + v.y + v.z + v.w;
            }
        }
        int suf = s;
#pragma unroll
        for (int off = 1; off < 32; off <<= 1) {
            int o = __shfl_down_sync(FULL, suf, off);
            if (lane + off < 32) suf += o;
        }
        unsigned m = __ballot_sync(FULL, suf >= TOPK);
        int T = 0;
        if (m) {
            int lstar = 31 - __clz(m);
            int sufn = __shfl_down_sync(FULL, suf, 1);
            int myabove = (lane == 31) ? 0 : sufn;
            int above = __shfl_sync(FULL, myabove, lstar);
            int b0 = lstar * SEG;
            int s2 = 0;
#pragma unroll
            for (int i = 0; i < SUB; i++) s2 += g_hist[b][b0 + lane * SUB + i];
            int suf2 = s2;
#pragma unroll
            for (int off = 1; off < 32; off <<= 1) {
                int o = __shfl_down_sync(FULL, suf2, off);
                if (lane + off < 32) suf2 += o;
            }
            unsigned m2 = __ballot_sync(FULL, above + suf2 >= TOPK);
            int l2 = 31 - __clz(m2);
            int sufn2 = __shfl_down_sync(FULL, suf2, 1);
            int myabove2 = (lane == 31) ? 0 : sufn2;
            int above2 = above + __shfl_sync(FULL, myabove2, l2);
            int Tl = 0;
            if (lane == l2) {
                int acc = above2;
                for (int bin = b0 + l2 * SUB + SUB - 1; bin >= b0 + l2 * SUB; bin--) {
                    acc += g_hist[b][bin];
                    if (acc >= TOPK) { Tl = bin; break; }
                }
            }
            T = __shfl_sync(FULL, Tl, l2);
        }
        if (lane == 0) sm.sthr[b] = T;
    }
    __syncthreads();

    // ================ P3: compact (warp-aggregated) ================
    for (int p = blockIdx.x * NTHR + tid; ; p += GRID * NTHR) {
        bool live = p < N;
        if (!__ballot_sync(FULL, live)) break;
        bool pass = false;
        int b = 0;
        unsigned long long key = 0ull;
        if (live) {
            float s = g_score[p];
            b = bidx[p];
            int bin = (int)(s * (float)HBINS);
            bin = max(0, min(HBINS - 1, bin));
            pass = bin >= sm.sthr[b];
            key = ((unsigned long long)__float_as_uint(s) << 32) | (unsigned)(~(unsigned)p);
        }
#pragma unroll
        for (int bb = 0; bb < NB; bb++) {
            unsigned m = __ballot_sync(FULL, pass && b == bb);
            if (m) {
                int leader = __ffs(m) - 1;
                int base = 0;
                if (lane == leader) base = atomicAdd(&g_cnt[bb], __popc(m));
                base = __shfl_sync(FULL, base, leader);
                if (pass && b == bb) {
                    int pos = base + __popc(m & ((1u << lane) - 1u));
                    if (pos < CAP) g_cand[bb][pos] = key;
                }
            }
        }
    }
    gridbar();  // BAR2

    // ================ P4: rank-and-scatter top-K (blocks 0..127) ================
    if (blockIdx.x < 128) {
        int b = blockIdx.x >> 5, chunk = blockIdx.x & 31;
        int cnt = min(g_cnt[b], CAP);
        for (int i = tid; i < cnt; i += NTHR) sm.u.sk[i] = g_cand[b][i];
        __syncthreads();
        for (int i = chunk * 32 + wid; i < cnt; i += 1024) {
            unsigned long long key = sm.u.sk[i];
            unsigned c = 0;
            for (int j = lane; j < cnt; j += 32)
                c += (sm.u.sk[j] > key) ? 1u : 0u;
            unsigned r = __reduce_add_sync(FULL, c);
            if (r < TOPK) g_sel[b][r] = key;
        }
    }
    gridbar();  // BAR3

    // ================ P5: decode selected boxes (blocks 0..127) ================
    if (blockIdx.x < 128) {
        for (int i = tid; i < 9 * 256; i += NTHR) {
            int o = i >> 8, f = i & 255;
            sm.u.wsm[o * 264 + f + (f >> 5)] = Wr[f * 9 + o];
        }
        if (tid == 0 && blockIdx.x < NB) g_cnt[blockIdx.x] = 0;  // re-zero for replay
        __syncthreads();
        int idx = blockIdx.x * 32 + wid;     // 0..4095
        int b = idx >> 10, t = idx & (TOPK - 1);
        unsigned long long key = g_sel[b][t];
        unsigned p = ~(unsigned)(key & 0xffffffffu);
        float score = __uint_as_float((unsigned)(key >> 32));
        bool valid = (key != 0ull) && (p < (unsigned)N);
        float bx[7];
        if (valid) {
            const float4* fp = (const float4*)(feat + (size_t)p * 256 + lane * 8);
            float4 f0 = fp[0], f1 = fp[1];
            float fv[8] = {f0.x, f0.y, f0.z, f0.w, f1.x, f1.y, f1.z, f1.w};
            float acc[9];
#pragma unroll
            for (int o = 0; o < 9; o++) acc[o] = 0.f;
#pragma unroll
            for (int o = 0; o < 9; o++)
#pragma unroll
                for (int k = 0; k < 8; k++) {
                    int f = 8 * lane + k;
                    float wv = sm.u.wsm[o * 264 + f + (f >> 5)];
                    acc[o] = fmaf(fv[k], wv, acc[o]);
                }
#pragma unroll
            for (int off = 16; off > 0; off >>= 1)
#pragma unroll
                for (int o = 0; o < 9; o++)
                    acc[o] += __shfl_xor_sync(FULL, acc[o], off);
            float r0 = acc[0] + br[0], r1 = acc[1] + br[1], r2 = acc[2] + br[2];
            float d0 = acc[3] + br[3], d1 = acc[4] + br[4], d2 = acc[5] + br[5];
            float a0 = acc[6] + br[6], a1 = acc[7] + br[7];
            int cx = coor[p * 2 + 0], cy = coor[p * 2 + 1];
            bx[0] = (float)cx * 0.8f + r0;
            bx[1] = (float)cy * 0.8f + r1;
            bx[2] = r2;
            bx[3] = expf(fminf(fmaxf(d0, -6.f), 6.f));
            bx[4] = expf(fminf(fmaxf(d1, -6.f), 6.f));
            bx[5] = expf(fminf(fmaxf(d2, -6.f), 6.f));
            bx[6] = atan2f(a0, a1);
        } else {
#pragma unroll
            for (int c = 0; c < 7; c++) bx[c] = 0.f;
            score = 0.f;
        }
        if (lane == 0) {
#pragma unroll
            for (int c = 0; c < 7; c++) g_top[b][t][c] = bx[c];
            g_top[b][t][7] = score;
            float x = bx[0], y = bx[1], l = bx[3], w = bx[4];
            g_nms[b][t][0] = x - l * 0.5f;
            g_nms[b][t][1] = x + l * 0.5f;
            g_nms[b][t][2] = y - w * 0.5f;
            g_nms[b][t][3] = y + w * 0.5f;
            g_nms[b][t][4] = l * w;
        }
    }
    gridbar();  // BAR4

    // ================ P6: IoU bitmask (blocks 0..127) + re-zero g_hist ================
    if (blockIdx.x < 128) {
        int b = blockIdx.x >> 5, rg = blockIdx.x & 31;
        for (int i = tid; i < TOPK; i += NTHR) {
            sm.u.iou.sx1[i] = g_nms[b][i][0];
            sm.u.iou.sx2[i] = g_nms[b][i][1];
            sm.u.iou.sy1[i] = g_nms[b][i][2];
            sm.u.iou.sy2[i] = g_nms[b][i][3];
            sm.u.iou.sa[i]  = g_nms[b][i][4];
        }
        __syncthreads();
        int col = tid, wp = tid >> 5;
        float cx1 = sm.u.iou.sx1[col], cx2 = sm.u.iou.sx2[col];
        float cy1 = sm.u.iou.sy1[col], cy2 = sm.u.iou.sy2[col], ca = sm.u.iou.sa[col];
        for (int rr = 0; rr < 32; rr++) {
            int r = rg * 32 + rr;
            float rx1 = sm.u.iou.sx1[r], rx2 = sm.u.iou.sx2[r];
            float ry1 = sm.u.iou.sy1[r], ry2 = sm.u.iou.sy2[r], ra = sm.u.iou.sa[r];
            float ix = fmaxf(fminf(rx2, cx2) - fmaxf(rx1, cx1), 0.f);
            float iy = fmaxf(fminf(ry2, cy2) - fmaxf(ry1, cy1), 0.f);
            float inter = ix * iy;
            float uni = fmaxf(ra + ca - inter, 1e-6f);
            bool sup = inter > THR * uni;
            unsigned bal = __ballot_sync(FULL, sup);
            if (lane == 0) g_mask[b][wp][r] = bal;
        }
        if (tid < 256) ((int*)g_hist)[blockIdx.x * 256 + tid] = 0;
    }
    gridbar();  // BAR5

    // ================ P7: sequential NMS + output (blocks 0..3) ================
    if (blockIdx.x >= NB) return;
    {
        int b = blockIdx.x;
        int t = tid;
        if (t == 0) sm.u.nms.scount = 0;
        if (t < 32) sm.u.nms.sremv[t] = 0;
        __syncthreads();
        {
            int r = t;
            unsigned v[32];
#pragma unroll
            for (int w = 0; w < 32; w++) v[w] = g_mask[b][w][r];
            int wd = r >> 5;
            unsigned above = ~((2u << (r & 31)) - 1u);
            unsigned dg = v[wd] & above;
            sm.u.nms.sdiag[r] = dg;
            unsigned hi = 0;
#pragma unroll
            for (int w = 0; w < 32; w++)
                if (w > wd) hi |= v[w];
            bool flag = (dg != 0u) || (hi != 0u);
            sm.u.nms.sflag[r] = (unsigned char)flag;
            int slot = -2;
            if (flag) {
                slot = atomicAdd(&sm.u.nms.scount, 1);
                if (slot < 256) {
#pragma unroll
                    for (int w = 0; w < 32; w++) sm.u.nms.srows[slot][w] = v[w];
                } else slot = -2;
            }
            sm.u.nms.sslot[r] = slot;
        }
        __syncthreads();

        if (t < 32) {
            int ln = t;
            for (int ch = 0; ch < 32; ch++) {
                unsigned cur = sm.u.nms.sremv[ch];
                int r = ch * 32 + ln;
                unsigned mym = sm.u.nms.sdiag[r];
                unsigned intra = __reduce_or_sync(FULL, mym);
                unsigned keepbits;
                if (intra == 0u) {
                    keepbits = ~cur;
                } else {
                    unsigned supp = cur;
                    keepbits = 0u;
                    for (int q = 0; q < 32; q++) {
                        unsigned m = __shfl_sync(FULL, mym, q);
                        if (!((supp >> q) & 1u)) { keepbits |= (1u << q); supp |= m; }
                    }
                }
                if (ln == 0) sm.u.nms.skeepw[ch] = keepbits;
                bool mykeep = (keepbits >> ln) & 1u;
                unsigned todo = __ballot_sync(FULL, mykeep && sm.u.nms.sflag[r]);
                while (todo) {
                    int q = __ffs(todo) - 1;
                    todo &= todo - 1;
                    int rr = ch * 32 + q;
                    int slot = sm.u.nms.sslot[rr];
                    unsigned v = (slot >= 0) ? sm.u.nms.srows[slot][ln] : g_mask[b][ln][rr];
                    sm.u.nms.sremv[ln] |= v;
                }
                __syncwarp();
            }
        }
        __syncthreads();

        {
            int r = t;
            float kp = ((sm.u.nms.skeepw[r >> 5] >> (r & 31)) & 1u) ? 1.f : 0.f;
#pragma unroll
            for (int c = 0; c < 8; c++)
                out[((size_t)b * TOPK + r) * 8 + c] = g_top[b][r][c] * kp;
            out[(size_t)NB * TOPK * 8 + (size_t)b * TOPK + r] = 0.f;
            out[(size_t)NB * TOPK * 8 + (size_t)NB * TOPK + (size_t)b * TOPK + r] = kp;
        }
    }
}

// ---------------- launch ----------------
extern "C" void kernel_launch(void* const* d_in, const int* in_sizes, int n_in,
                              void* d_out, int out_size) {
    const float* feat = (const float*)d_in[0];
    const int*   bidx = (const int*)d_in[1];
    const int*   coor = (const int*)d_in[2];
    const float* Wc   = (const float*)d_in[3];
    const float* bc   = (const float*)d_in[4];
    const float* Wr   = (const float*)d_in[5];
    const float* br   = (const float*)d_in[6];
    float* out = (float*)d_out;
    int N = in_sizes[0] / 256;

    k_all<<<GRID, NTHR>>>(feat, bidx, coor, Wc, bc, Wr, br, out, N);
}